// round 10
// baseline (speedup 1.0000x reference)
#include <cuda_runtime.h>
#include <math.h>
#include <stdint.h>

#define NB 2048
#define ND 1024
#define NH 2048
#define NO 512
#define NE 8
#define KSPLIT2 4

#define STAGES 3
#define A_STAGE_B (128 * 144)  // 128 rows * 36 words * 4B  (BK=32 + 4 pad)
#define B_STAGE_B (32 * 544)   // 32 k-rows * 136 words * 4B
#define SM_A 1024
#define SM_B (SM_A + STAGES * A_STAGE_B)
#define SMEM_TOTAL (SM_B + STAGES * B_STAGE_B)   // 108544+1024 B -> 2 CTAs/SM

// ---------------- scratch ----------------
__device__ float g_H[(size_t)NE * 2048 * NH];                // expert hidden (slot-major)
__device__ float g_Lp[(size_t)KSPLIT2 * NE * 2048 * NO];     // split-K partial logits
__device__ int   g_count[NE];
__device__ int   g_rows[NE * 2048];
__device__ int   g_slot[NB * 2];
__device__ float g_gate[NB * 2];

#define PARTSZ ((size_t)NE * 2048 * NO)

// ---------------- helpers ----------------
__device__ __forceinline__ uint32_t smem_to_u32(const void* p) {
    uint32_t a;
    asm("{ .reg .u64 t; cvta.to.shared.u64 t, %1; cvt.u32.u64 %0, t; }" : "=r"(a) : "l"(p));
    return a;
}
__device__ __forceinline__ void cpa16(uint32_t dst, const void* src) {
    asm volatile("cp.async.ca.shared.global [%0], [%1], 16;" :: "r"(dst), "l"(src));
}
#define CP_COMMIT() asm volatile("cp.async.commit_group;" ::: "memory")
#define CP_WAIT(n)  asm volatile("cp.async.wait_group %0;" :: "n"(n) : "memory")
__device__ __forceinline__ uint32_t lds32(uint32_t a) {
    uint32_t v;
    asm volatile("ld.shared.b32 %0, [%1];" : "=r"(v) : "r"(a));
    return v;
}
__device__ __forceinline__ void mma8(float* c, const uint32_t* a, const uint32_t* b) {
    asm volatile(
        "mma.sync.aligned.m16n8k8.row.col.f32.tf32.tf32.f32 "
        "{%0,%1,%2,%3}, {%4,%5,%6,%7}, {%8,%9}, {%0,%1,%2,%3};"
        : "+f"(c[0]), "+f"(c[1]), "+f"(c[2]), "+f"(c[3])
        : "r"(a[0]), "r"(a[1]), "r"(a[2]), "r"(a[3]), "r"(b[0]), "r"(b[1]));
}

__global__ void zero_counts_kernel() {
    if (threadIdx.x < NE) g_count[threadIdx.x] = 0;
}

// One warp per token: logits, top-2 (first-index ties), softmax-of-2, scatter.
__global__ void gate_kernel(const float* __restrict__ x, const float* __restrict__ wg) {
    int warp = threadIdx.x >> 5, lane = threadIdx.x & 31;
    int b = blockIdx.x * 8 + warp;
    float acc[NE];
#pragma unroll
    for (int e = 0; e < NE; e++) acc[e] = 0.f;
    const float* xr = x + (size_t)b * ND;
    for (int d = lane; d < ND; d += 32) {
        float xv = xr[d];
#pragma unroll
        for (int e = 0; e < NE; e++) acc[e] += xv * wg[d * NE + e];
    }
#pragma unroll
    for (int e = 0; e < NE; e++)
#pragma unroll
        for (int off = 16; off; off >>= 1)
            acc[e] += __shfl_xor_sync(0xffffffffu, acc[e], off);
    if (lane == 0) {
        int i0 = 0; float l0 = acc[0];
#pragma unroll
        for (int e = 1; e < NE; e++) if (acc[e] > l0) { l0 = acc[e]; i0 = e; }
        int i1 = (i0 == 0) ? 1 : 0;
        float l1 = acc[i1];
#pragma unroll
        for (int e = 0; e < NE; e++)
            if (e != i0 && acc[e] > l1) { l1 = acc[e]; i1 = e; }
        float ex = expf(l1 - l0);
        float inv = 1.f / (1.f + ex);
        int p0 = atomicAdd(&g_count[i0], 1);
        g_rows[i0 * 2048 + p0] = b;
        g_slot[b * 2 + 0] = i0 * 2048 + p0;
        g_gate[b * 2 + 0] = inv;
        int p1 = atomicAdd(&g_count[i1], 1);
        g_rows[i1 * 2048 + p1] = b;
        g_slot[b * 2 + 1] = i1 * 2048 + p1;
        g_gate[b * 2 + 1] = ex * inv;
    }
}

// ---------------- TF32 grouped GEMM: CTA 128x128, 256 threads, 2 CTAs/SM, BK=32, 3-stage ----------------
// 8 warps in 2x4 grid; warp tile 64x32. KSPL>1: split-K over blockIdx.z.
template <int KCHUNK, int KFULL, int LDA, int LDB, int LDC, int KSPL, bool LUT, bool GELU>
__global__ __launch_bounds__(256, 2) void gemm_tf32(
    const float* __restrict__ Ain,   // x (LUT) / unused
    const float* __restrict__ Bin,   // w1 / w2 (expert-major)
    const float* __restrict__ bias)  // b1 (gemm2: unused)
{
    int e = blockIdx.z / KSPL;
    int ksp = blockIdx.z % KSPL;
    int cnt = g_count[e];
    int t0 = blockIdx.y * 128;
    if (t0 >= cnt) return;
    int n0 = blockIdx.x * 128;
    int kbase = ksp * KCHUNK;

    extern __shared__ char smem[];
    uint32_t sb = smem_to_u32(smem);
    int* rowsLUT = (int*)smem;
    int tid = threadIdx.x;
    int lane = tid & 31, wid = tid >> 5;
    int wm = wid >> 2, wn = wid & 3;

    if (LUT && tid < 128) rowsLUT[tid] = g_rows[e * 2048 + min(t0 + tid, cnt - 1)];
    __syncthreads();

    // cp.async setup (per 32-k stage): A = 4 x 16B per thread, B = 4 x 16B per thread
    int ar = tid >> 1;                 // row 0..127 (2 threads per row)
    const float* abase;
    if (LUT) abase = Ain + (size_t)rowsLUT[ar] * LDA;
    else     abase = (const float*)g_H + (size_t)(e * 2048 + t0 + ar) * LDA;
    const float* aptr0 = abase + kbase + (tid & 1) * 4;          // + j*8 per chunk
    uint32_t adst0 = sb + SM_A + ar * 144 + (tid & 1) * 16;      // + j*32 per chunk

    int kb = tid >> 5;                 // 0..7
    const float* Bsrc = Bin + (size_t)e * KFULL * LDB + (size_t)kbase * LDB + n0 + lane * 4;
    const float* bptr0 = Bsrc + (size_t)kb * LDB;                // + j*8*LDB per chunk
    uint32_t bdst0 = sb + SM_B + kb * 544 + lane * 16;           // + j*4352 per chunk

    float c[4][4][4];
#pragma unroll
    for (int mt = 0; mt < 4; mt++)
#pragma unroll
        for (int nt = 0; nt < 4; nt++)
#pragma unroll
            for (int q = 0; q < 4; q++) c[mt][nt][q] = 0.f;

    // prologue
#pragma unroll
    for (int s = 0; s < STAGES - 1; s++) {
        int k0 = s * 32;
#pragma unroll
        for (int j = 0; j < 4; j++) {
            cpa16(adst0 + s * A_STAGE_B + j * 32, aptr0 + k0 + j * 8);
            cpa16(bdst0 + s * B_STAGE_B + j * 4352, bptr0 + (size_t)(k0 + j * 8) * LDB);
        }
        CP_COMMIT();
    }

    uint32_t a_frag_base = sb + SM_A + ((wm * 64 + (lane >> 2)) * 36 + (lane & 3)) * 4;
    uint32_t b_frag_base = sb + SM_B + ((lane & 3) * 136 + wn * 32 + (lane >> 2)) * 4;

    const int NK = KCHUNK / 32;
    for (int kt = 0; kt < NK; kt++) {
        CP_WAIT(STAGES - 2);
        __syncthreads();
        int s = kt % STAGES;
        int knext = kt + STAGES - 1;
        if (knext < NK) {
            int sn = knext % STAGES;
            int k0 = knext * 32;
#pragma unroll
            for (int j = 0; j < 4; j++) {
                cpa16(adst0 + sn * A_STAGE_B + j * 32, aptr0 + k0 + j * 8);
                cpa16(bdst0 + sn * B_STAGE_B + j * 4352, bptr0 + (size_t)(k0 + j * 8) * LDB);
            }
            CP_COMMIT();
        }
        uint32_t ab = a_frag_base + s * A_STAGE_B;
        uint32_t bb = b_frag_base + s * B_STAGE_B;
#pragma unroll
        for (int ks = 0; ks < 4; ks++) {
            uint32_t af[4][4], bf[4][2];
#pragma unroll
            for (int mt = 0; mt < 4; mt++) {
                uint32_t ad = ab + mt * 2304 + ks * 32;    // 16 rows*144B, 8 k*4B
                af[mt][0] = lds32(ad);
                af[mt][1] = lds32(ad + 1152);              // +8 rows
                af[mt][2] = lds32(ad + 16);                // +4 k
                af[mt][3] = lds32(ad + 1168);
            }
#pragma unroll
            for (int nt = 0; nt < 4; nt++) {
                uint32_t bd = bb + ks * 4352 + nt * 32;    // 8 k-rows*544B
                bf[nt][0] = lds32(bd);
                bf[nt][1] = lds32(bd + 2176);              // +4 k-rows
            }
#pragma unroll
            for (int mt = 0; mt < 4; mt++)
#pragma unroll
                for (int nt = 0; nt < 4; nt++)
                    mma8(c[mt][nt], af[mt], bf[nt]);
        }
    }

    // epilogue
#pragma unroll
    for (int mt = 0; mt < 4; mt++) {
#pragma unroll
        for (int h = 0; h < 2; h++) {
            int lr = wm * 64 + mt * 16 + (lane >> 2) + h * 8;
            if (t0 + lr < cnt) {
                size_t rowoff = (size_t)(e * 2048 + t0 + lr) * LDC + n0 + wn * 32 + (lane & 3) * 2;
                if (GELU) {
                    const float* bias_e = bias + (size_t)e * LDC + n0 + wn * 32 + (lane & 3) * 2;
                    float* dst = g_H + rowoff;
#pragma unroll
                    for (int nt = 0; nt < 4; nt++) {
                        float2 bv = *(const float2*)(bias_e + nt * 8);
                        float v0 = c[mt][nt][h * 2 + 0] + bv.x;
                        float v1 = c[mt][nt][h * 2 + 1] + bv.y;
                        v0 = 0.5f * v0 * (1.0f + erff(v0 * 0.7071067811865476f));
                        v1 = 0.5f * v1 * (1.0f + erff(v1 * 0.7071067811865476f));
                        *(float2*)(dst + nt * 8) = make_float2(v0, v1);
                    }
                } else {
                    float* dst = g_Lp + (size_t)ksp * PARTSZ + rowoff;
#pragma unroll
                    for (int nt = 0; nt < 4; nt++)
                        *(float2*)(dst + nt * 8) =
                            make_float2(c[mt][nt][h * 2 + 0], c[mt][nt][h * 2 + 1]);
                }
            }
        }
    }
}

// Per-token: sum split-K partials + bias, logsumexp both expert rows, combine, log.
__global__ void combine_kernel(float* __restrict__ out, const float* __restrict__ b2) {
    int b = blockIdx.x;
    int tid = threadIdx.x;
    __shared__ float sred[256];
    int s0 = g_slot[b * 2], s1 = g_slot[b * 2 + 1];
    int e0 = s0 >> 11, e1 = s1 >> 11;
    float gg0 = g_gate[b * 2], gg1 = g_gate[b * 2 + 1];

    float v00, v01, v10, v11;
    {
        size_t r0 = (size_t)s0 * NO, r1 = (size_t)s1 * NO;
        v00 = b2[e0 * NO + tid]; v01 = b2[e0 * NO + tid + 256];
        v10 = b2[e1 * NO + tid]; v11 = b2[e1 * NO + tid + 256];
#pragma unroll
        for (int p = 0; p < KSPLIT2; p++) {
            const float* P = g_Lp + (size_t)p * PARTSZ;
            v00 += P[r0 + tid]; v01 += P[r0 + tid + 256];
            v10 += P[r1 + tid]; v11 += P[r1 + tid + 256];
        }
    }

    sred[tid] = fmaxf(v00, v01); __syncthreads();
    for (int s = 128; s; s >>= 1) { if (tid < s) sred[tid] = fmaxf(sred[tid], sred[tid + s]); __syncthreads(); }
    float m0 = sred[0]; __syncthreads();
    sred[tid] = expf(v00 - m0) + expf(v01 - m0); __syncthreads();
    for (int s = 128; s; s >>= 1) { if (tid < s) sred[tid] += sred[tid + s]; __syncthreads(); }
    float lse0 = m0 + logf(sred[0]); __syncthreads();

    sred[tid] = fmaxf(v10, v11); __syncthreads();
    for (int s = 128; s; s >>= 1) { if (tid < s) sred[tid] = fmaxf(sred[tid], sred[tid + s]); __syncthreads(); }
    float m1 = sred[0]; __syncthreads();
    sred[tid] = expf(v10 - m1) + expf(v11 - m1); __syncthreads();
    for (int s = 128; s; s >>= 1) { if (tid < s) sred[tid] += sred[tid + s]; __syncthreads(); }
    float lse1 = m1 + logf(sred[0]);

    out[(size_t)b * NO + tid]       = logf(gg0 * expf(v00 - lse0) + gg1 * expf(v10 - lse1));
    out[(size_t)b * NO + tid + 256] = logf(gg0 * expf(v01 - lse0) + gg1 * expf(v11 - lse1));
}

extern "C" void kernel_launch(void* const* d_in, const int* in_sizes, int n_in,
                              void* d_out, int out_size) {
    const float* x  = (const float*)d_in[0];
    const float* wg = (const float*)d_in[1];
    const float* w1 = (const float*)d_in[2];
    const float* b1 = (const float*)d_in[3];
    const float* w2 = (const float*)d_in[4];
    const float* b2 = (const float*)d_in[5];
    float* out = (float*)d_out;

    auto k1 = gemm_tf32<ND, ND, ND, NH, NH, 1, true, true>;
    auto k2 = gemm_tf32<NH / KSPLIT2, NH, NH, NO, NO, KSPLIT2, false, false>;
    cudaFuncSetAttribute((const void*)k1, cudaFuncAttributeMaxDynamicSharedMemorySize, SMEM_TOTAL);
    cudaFuncSetAttribute((const void*)k2, cudaFuncAttributeMaxDynamicSharedMemorySize, SMEM_TOTAL);

    zero_counts_kernel<<<1, 32>>>();
    gate_kernel<<<NB / 8, 256>>>(x, wg);
    k1<<<dim3(NH / 128, 16, NE), 256, SMEM_TOTAL>>>(x, w1, b1);
    k2<<<dim3(NO / 128, 16, NE * KSPLIT2), 256, SMEM_TOTAL>>>(x, w2, b2);
    combine_kernel<<<NB, 256>>>(out, b2);
}

// round 11
// speedup vs baseline: 1.2630x; 1.2630x over previous
#include <cuda_runtime.h>
#include <math.h>
#include <stdint.h>

#define NB 2048
#define ND 1024
#define NH 2048
#define NO 512
#define NE 8
#define KSPLIT2 4

#define STAGES 3
#define A_STAGE_B (128 * 80)   // 128 rows * 20 words * 4B
#define B_STAGE_B (16 * 544)   // 16 k-rows * 136 words * 4B
#define SM_A 1024
#define SM_B (SM_A + STAGES * A_STAGE_B)
#define SMEM_TOTAL (SM_B + STAGES * B_STAGE_B)   // 57856 B -> 2 CTAs/SM

// ---------------- scratch ----------------
__device__ float g_H[(size_t)NE * 2048 * NH];                // expert hidden (slot-major)
__device__ float g_Lp[(size_t)KSPLIT2 * NE * 2048 * NO];     // split-K partial logits
__device__ int   g_count[NE];
__device__ int   g_rows[NE * 2048];
__device__ int   g_slot[NB * 2];
__device__ float g_gate[NB * 2];

#define PARTSZ ((size_t)NE * 2048 * NO)

// ---------------- helpers ----------------
__device__ __forceinline__ uint32_t smem_to_u32(const void* p) {
    uint32_t a;
    asm("{ .reg .u64 t; cvta.to.shared.u64 t, %1; cvt.u32.u64 %0, t; }" : "=r"(a) : "l"(p));
    return a;
}
__device__ __forceinline__ void cpa16(uint32_t dst, const void* src) {
    asm volatile("cp.async.ca.shared.global [%0], [%1], 16;" :: "r"(dst), "l"(src));
}
#define CP_COMMIT() asm volatile("cp.async.commit_group;" ::: "memory")
#define CP_WAIT(n)  asm volatile("cp.async.wait_group %0;" :: "n"(n) : "memory")
__device__ __forceinline__ uint32_t lds32(uint32_t a) {
    uint32_t v;
    asm volatile("ld.shared.b32 %0, [%1];" : "=r"(v) : "r"(a));
    return v;
}
__device__ __forceinline__ void ldsm4(uint32_t* r, uint32_t a) {
    asm volatile("ldmatrix.sync.aligned.m8n8.x4.shared.b16 {%0,%1,%2,%3}, [%4];"
        : "=r"(r[0]), "=r"(r[1]), "=r"(r[2]), "=r"(r[3]) : "r"(a));
}
__device__ __forceinline__ void mma8(float* c, const uint32_t* a, const uint32_t* b) {
    asm volatile(
        "mma.sync.aligned.m16n8k8.row.col.f32.tf32.tf32.f32 "
        "{%0,%1,%2,%3}, {%4,%5,%6,%7}, {%8,%9}, {%0,%1,%2,%3};"
        : "+f"(c[0]), "+f"(c[1]), "+f"(c[2]), "+f"(c[3])
        : "r"(a[0]), "r"(a[1]), "r"(a[2]), "r"(a[3]), "r"(b[0]), "r"(b[1]));
}

__global__ void zero_counts_kernel() {
    if (threadIdx.x < NE) g_count[threadIdx.x] = 0;
}

// One warp per token: logits, top-2 (first-index ties), softmax-of-2, scatter.
__global__ void gate_kernel(const float* __restrict__ x, const float* __restrict__ wg) {
    int warp = threadIdx.x >> 5, lane = threadIdx.x & 31;
    int b = blockIdx.x * 8 + warp;
    float acc[NE];
#pragma unroll
    for (int e = 0; e < NE; e++) acc[e] = 0.f;
    const float* xr = x + (size_t)b * ND;
    for (int d = lane; d < ND; d += 32) {
        float xv = xr[d];
#pragma unroll
        for (int e = 0; e < NE; e++) acc[e] += xv * wg[d * NE + e];
    }
#pragma unroll
    for (int e = 0; e < NE; e++)
#pragma unroll
        for (int off = 16; off; off >>= 1)
            acc[e] += __shfl_xor_sync(0xffffffffu, acc[e], off);
    if (lane == 0) {
        int i0 = 0; float l0 = acc[0];
#pragma unroll
        for (int e = 1; e < NE; e++) if (acc[e] > l0) { l0 = acc[e]; i0 = e; }
        int i1 = (i0 == 0) ? 1 : 0;
        float l1 = acc[i1];
#pragma unroll
        for (int e = 0; e < NE; e++)
            if (e != i0 && acc[e] > l1) { l1 = acc[e]; i1 = e; }
        float ex = expf(l1 - l0);
        float inv = 1.f / (1.f + ex);
        int p0 = atomicAdd(&g_count[i0], 1);
        g_rows[i0 * 2048 + p0] = b;
        g_slot[b * 2 + 0] = i0 * 2048 + p0;
        g_gate[b * 2 + 0] = inv;
        int p1 = atomicAdd(&g_count[i1], 1);
        g_rows[i1 * 2048 + p1] = b;
        g_slot[b * 2 + 1] = i1 * 2048 + p1;
        g_gate[b * 2 + 1] = ex * inv;
    }
}

// ---------------- TF32 grouped GEMM: CTA 128x128, 256 threads, 2 CTAs/SM, BK=16, 3-stage ----------------
// 8 warps in 2x4 grid; warp tile 64x32. A fragments via ldmatrix.x4. KSPL>1: split-K over blockIdx.z.
template <int KCHUNK, int KFULL, int LDA, int LDB, int LDC, int KSPL, bool LUT, bool GELU>
__global__ __launch_bounds__(256, 2) void gemm_tf32(
    const float* __restrict__ Ain,   // x (LUT) / unused
    const float* __restrict__ Bin,   // w1 / w2 (expert-major)
    const float* __restrict__ bias)  // b1 (gemm2: unused)
{
    int e = blockIdx.z / KSPL;
    int ksp = blockIdx.z % KSPL;
    int cnt = g_count[e];
    int t0 = blockIdx.y * 128;
    if (t0 >= cnt) return;
    int n0 = blockIdx.x * 128;
    int kbase = ksp * KCHUNK;

    extern __shared__ char smem[];
    uint32_t sb = smem_to_u32(smem);
    int* rowsLUT = (int*)smem;
    int tid = threadIdx.x;
    int lane = tid & 31, wid = tid >> 5;
    int wm = wid >> 2, wn = wid & 3;

    if (LUT && tid < 128) rowsLUT[tid] = g_rows[e * 2048 + min(t0 + tid, cnt - 1)];
    __syncthreads();

    // cp.async setup: A = 2 x 16B per thread (rows r, r+64), B = 2 x 16B per thread
    const float* aptr[2];
    uint32_t adst[2];
#pragma unroll
    for (int i = 0; i < 2; i++) {
        int r = (tid >> 2) + 64 * i;
        const float* base;
        if (LUT) base = Ain + (size_t)rowsLUT[r] * LDA;
        else     base = (const float*)g_H + (size_t)(e * 2048 + t0 + r) * LDA;
        aptr[i] = base + kbase + (tid & 3) * 4;
        adst[i] = sb + SM_A + r * 80 + (tid & 3) * 16;
    }
    int kb = tid >> 5;
    const float* Bsrc = Bin + (size_t)e * KFULL * LDB + (size_t)kbase * LDB + n0 + (tid & 31) * 4;
    const float* bptr[2];
    uint32_t bdst[2];
#pragma unroll
    for (int j = 0; j < 2; j++) {
        bptr[j] = Bsrc + (size_t)(kb + 8 * j) * LDB;
        bdst[j] = sb + SM_B + (kb + 8 * j) * 544 + (tid & 31) * 16;
    }

    float c[4][4][4];
#pragma unroll
    for (int mt = 0; mt < 4; mt++)
#pragma unroll
        for (int nt = 0; nt < 4; nt++)
#pragma unroll
            for (int q = 0; q < 4; q++) c[mt][nt][q] = 0.f;

    // prologue
#pragma unroll
    for (int s = 0; s < STAGES - 1; s++) {
        int k0 = s * 16;
#pragma unroll
        for (int i = 0; i < 2; i++) cpa16(adst[i] + s * A_STAGE_B, aptr[i] + k0);
#pragma unroll
        for (int j = 0; j < 2; j++) cpa16(bdst[j] + s * B_STAGE_B, bptr[j] + (size_t)k0 * LDB);
        CP_COMMIT();
    }

    // ldmatrix lane base for A: matrices m0=rows g/k0-3, m1=g+8/k0-3, m2=g/k4-7, m3=g+8/k4-7
    int a_lm_row = wm * 64 + (lane & 7) + ((lane >> 3) & 1) * 8;
    uint32_t a_lm_base = sb + SM_A + a_lm_row * 80 + (lane >> 4) * 16;
    uint32_t b_frag_base = sb + SM_B + ((lane & 3) * 136 + wn * 32 + (lane >> 2)) * 4;

    const int NK = KCHUNK / 16;
    for (int kt = 0; kt < NK; kt++) {
        CP_WAIT(STAGES - 2);
        __syncthreads();
        int s = kt % STAGES;
        int knext = kt + STAGES - 1;
        if (knext < NK) {
            int sn = knext % STAGES;
            int k0 = knext * 16;
#pragma unroll
            for (int i = 0; i < 2; i++) cpa16(adst[i] + sn * A_STAGE_B, aptr[i] + k0);
#pragma unroll
            for (int j = 0; j < 2; j++) cpa16(bdst[j] + sn * B_STAGE_B, bptr[j] + (size_t)k0 * LDB);
            CP_COMMIT();
        }
        uint32_t ab = a_lm_base + s * A_STAGE_B;
        uint32_t bb = b_frag_base + s * B_STAGE_B;
#pragma unroll
        for (int ks = 0; ks < 2; ks++) {
            uint32_t af[4][4], bf[4][2];
#pragma unroll
            for (int mt = 0; mt < 4; mt++)
                ldsm4(af[mt], ab + mt * 1280 + ks * 32);
#pragma unroll
            for (int nt = 0; nt < 4; nt++) {
                uint32_t bd = bb + ks * 4352 + nt * 32;
                bf[nt][0] = lds32(bd);
                bf[nt][1] = lds32(bd + 2176);
            }
#pragma unroll
            for (int mt = 0; mt < 4; mt++)
#pragma unroll
                for (int nt = 0; nt < 4; nt++)
                    mma8(c[mt][nt], af[mt], bf[nt]);
        }
    }

    // epilogue
#pragma unroll
    for (int mt = 0; mt < 4; mt++) {
#pragma unroll
        for (int h = 0; h < 2; h++) {
            int lr = wm * 64 + mt * 16 + (lane >> 2) + h * 8;
            if (t0 + lr < cnt) {
                size_t rowoff = (size_t)(e * 2048 + t0 + lr) * LDC + n0 + wn * 32 + (lane & 3) * 2;
                if (GELU) {
                    const float* bias_e = bias + (size_t)e * LDC + n0 + wn * 32 + (lane & 3) * 2;
                    float* dst = g_H + rowoff;
#pragma unroll
                    for (int nt = 0; nt < 4; nt++) {
                        float2 bv = *(const float2*)(bias_e + nt * 8);
                        float v0 = c[mt][nt][h * 2 + 0] + bv.x;
                        float v1 = c[mt][nt][h * 2 + 1] + bv.y;
                        v0 = 0.5f * v0 * (1.0f + erff(v0 * 0.7071067811865476f));
                        v1 = 0.5f * v1 * (1.0f + erff(v1 * 0.7071067811865476f));
                        *(float2*)(dst + nt * 8) = make_float2(v0, v1);
                    }
                } else {
                    float* dst = g_Lp + (size_t)ksp * PARTSZ + rowoff;
#pragma unroll
                    for (int nt = 0; nt < 4; nt++)
                        *(float2*)(dst + nt * 8) =
                            make_float2(c[mt][nt][h * 2 + 0], c[mt][nt][h * 2 + 1]);
                }
            }
        }
    }
}

// Per-token: sum split-K partials + bias, logsumexp both expert rows, combine, log.
__global__ void combine_kernel(float* __restrict__ out, const float* __restrict__ b2) {
    int b = blockIdx.x;
    int tid = threadIdx.x;
    __shared__ float sred[256];
    int s0 = g_slot[b * 2], s1 = g_slot[b * 2 + 1];
    int e0 = s0 >> 11, e1 = s1 >> 11;
    float gg0 = g_gate[b * 2], gg1 = g_gate[b * 2 + 1];

    float v00, v01, v10, v11;
    {
        size_t r0 = (size_t)s0 * NO, r1 = (size_t)s1 * NO;
        v00 = b2[e0 * NO + tid]; v01 = b2[e0 * NO + tid + 256];
        v10 = b2[e1 * NO + tid]; v11 = b2[e1 * NO + tid + 256];
#pragma unroll
        for (int p = 0; p < KSPLIT2; p++) {
            const float* P = g_Lp + (size_t)p * PARTSZ;
            v00 += P[r0 + tid]; v01 += P[r0 + tid + 256];
            v10 += P[r1 + tid]; v11 += P[r1 + tid + 256];
        }
    }

    sred[tid] = fmaxf(v00, v01); __syncthreads();
    for (int s = 128; s; s >>= 1) { if (tid < s) sred[tid] = fmaxf(sred[tid], sred[tid + s]); __syncthreads(); }
    float m0 = sred[0]; __syncthreads();
    sred[tid] = expf(v00 - m0) + expf(v01 - m0); __syncthreads();
    for (int s = 128; s; s >>= 1) { if (tid < s) sred[tid] += sred[tid + s]; __syncthreads(); }
    float lse0 = m0 + logf(sred[0]); __syncthreads();

    sred[tid] = fmaxf(v10, v11); __syncthreads();
    for (int s = 128; s; s >>= 1) { if (tid < s) sred[tid] = fmaxf(sred[tid], sred[tid + s]); __syncthreads(); }
    float m1 = sred[0]; __syncthreads();
    sred[tid] = expf(v10 - m1) + expf(v11 - m1); __syncthreads();
    for (int s = 128; s; s >>= 1) { if (tid < s) sred[tid] += sred[tid + s]; __syncthreads(); }
    float lse1 = m1 + logf(sred[0]);

    out[(size_t)b * NO + tid]       = logf(gg0 * expf(v00 - lse0) + gg1 * expf(v10 - lse1));
    out[(size_t)b * NO + tid + 256] = logf(gg0 * expf(v01 - lse0) + gg1 * expf(v11 - lse1));
}

extern "C" void kernel_launch(void* const* d_in, const int* in_sizes, int n_in,
                              void* d_out, int out_size) {
    const float* x  = (const float*)d_in[0];
    const float* wg = (const float*)d_in[1];
    const float* w1 = (const float*)d_in[2];
    const float* b1 = (const float*)d_in[3];
    const float* w2 = (const float*)d_in[4];
    const float* b2 = (const float*)d_in[5];
    float* out = (float*)d_out;

    auto k1 = gemm_tf32<ND, ND, ND, NH, NH, 1, true, true>;
    auto k2 = gemm_tf32<NH / KSPLIT2, NH, NH, NO, NO, KSPLIT2, false, false>;
    cudaFuncSetAttribute((const void*)k1, cudaFuncAttributeMaxDynamicSharedMemorySize, SMEM_TOTAL);
    cudaFuncSetAttribute((const void*)k2, cudaFuncAttributeMaxDynamicSharedMemorySize, SMEM_TOTAL);

    zero_counts_kernel<<<1, 32>>>();
    gate_kernel<<<NB / 8, 256>>>(x, wg);
    k1<<<dim3(NH / 128, 16, NE), 256, SMEM_TOTAL>>>(x, w1, b1);
    k2<<<dim3(NO / 128, 16, NE * KSPLIT2), 256, SMEM_TOTAL>>>(x, w2, b2);
    combine_kernel<<<NB, 256>>>(out, b2);
}

// round 12
// speedup vs baseline: 1.2704x; 1.0058x over previous
#include <cuda_runtime.h>
#include <math.h>
#include <stdint.h>

#define NB 2048
#define ND 1024
#define NH 2048
#define NO 512
#define NE 8
#define KSPLIT2 4

#define STAGES 4
#define A_STAGE_B (128 * 80)   // 128 rows * 20 words * 4B
#define B_STAGE_B (16 * 544)   // 16 k-rows * 136 words * 4B
#define SM_A 1024
#define SM_B (SM_A + STAGES * A_STAGE_B)
#define SMEM_TOTAL (SM_B + STAGES * B_STAGE_B)   // 76800 B -> 2 CTAs/SM

// ---------------- scratch ----------------
__device__ float g_H[(size_t)NE * 2048 * NH];                // expert hidden (slot-major)
__device__ float g_Lp[(size_t)KSPLIT2 * NE * 2048 * NO];     // split-K partial logits
__device__ int   g_count[NE];
__device__ int   g_rows[NE * 2048];
__device__ int   g_slot[NB * 2];
__device__ float g_gate[NB * 2];

#define PARTSZ ((size_t)NE * 2048 * NO)

// ---------------- helpers ----------------
__device__ __forceinline__ uint32_t smem_to_u32(const void* p) {
    uint32_t a;
    asm("{ .reg .u64 t; cvta.to.shared.u64 t, %1; cvt.u32.u64 %0, t; }" : "=r"(a) : "l"(p));
    return a;
}
__device__ __forceinline__ void cpa16(uint32_t dst, const void* src) {
    asm volatile("cp.async.cg.shared.global [%0], [%1], 16;" :: "r"(dst), "l"(src));
}
#define CP_COMMIT() asm volatile("cp.async.commit_group;" ::: "memory")
#define CP_WAIT(n)  asm volatile("cp.async.wait_group %0;" :: "n"(n) : "memory")
__device__ __forceinline__ uint32_t lds32(uint32_t a) {
    uint32_t v;
    asm volatile("ld.shared.b32 %0, [%1];" : "=r"(v) : "r"(a));
    return v;
}
__device__ __forceinline__ void ldsm4(uint32_t* r, uint32_t a) {
    asm volatile("ldmatrix.sync.aligned.m8n8.x4.shared.b16 {%0,%1,%2,%3}, [%4];"
        : "=r"(r[0]), "=r"(r[1]), "=r"(r[2]), "=r"(r[3]) : "r"(a));
}
__device__ __forceinline__ void mma8(float* c, const uint32_t* a, const uint32_t* b) {
    asm volatile(
        "mma.sync.aligned.m16n8k8.row.col.f32.tf32.tf32.f32 "
        "{%0,%1,%2,%3}, {%4,%5,%6,%7}, {%8,%9}, {%0,%1,%2,%3};"
        : "+f"(c[0]), "+f"(c[1]), "+f"(c[2]), "+f"(c[3])
        : "r"(a[0]), "r"(a[1]), "r"(a[2]), "r"(a[3]), "r"(b[0]), "r"(b[1]));
}

__global__ void zero_counts_kernel() {
    if (threadIdx.x < NE) g_count[threadIdx.x] = 0;
}

// One warp per token: logits, top-2 (first-index ties), softmax-of-2, scatter.
__global__ void gate_kernel(const float* __restrict__ x, const float* __restrict__ wg) {
    int warp = threadIdx.x >> 5, lane = threadIdx.x & 31;
    int b = blockIdx.x * 8 + warp;
    float acc[NE];
#pragma unroll
    for (int e = 0; e < NE; e++) acc[e] = 0.f;
    const float* xr = x + (size_t)b * ND;
    for (int d = lane; d < ND; d += 32) {
        float xv = xr[d];
#pragma unroll
        for (int e = 0; e < NE; e++) acc[e] += xv * wg[d * NE + e];
    }
#pragma unroll
    for (int e = 0; e < NE; e++)
#pragma unroll
        for (int off = 16; off; off >>= 1)
            acc[e] += __shfl_xor_sync(0xffffffffu, acc[e], off);
    if (lane == 0) {
        int i0 = 0; float l0 = acc[0];
#pragma unroll
        for (int e = 1; e < NE; e++) if (acc[e] > l0) { l0 = acc[e]; i0 = e; }
        int i1 = (i0 == 0) ? 1 : 0;
        float l1 = acc[i1];
#pragma unroll
        for (int e = 0; e < NE; e++)
            if (e != i0 && acc[e] > l1) { l1 = acc[e]; i1 = e; }
        float ex = expf(l1 - l0);
        float inv = 1.f / (1.f + ex);
        int p0 = atomicAdd(&g_count[i0], 1);
        g_rows[i0 * 2048 + p0] = b;
        g_slot[b * 2 + 0] = i0 * 2048 + p0;
        g_gate[b * 2 + 0] = inv;
        int p1 = atomicAdd(&g_count[i1], 1);
        g_rows[i1 * 2048 + p1] = b;
        g_slot[b * 2 + 1] = i1 * 2048 + p1;
        g_gate[b * 2 + 1] = ex * inv;
    }
}

// ---------------- TF32 grouped GEMM: CTA 128x128, 256 threads, 2 CTAs/SM, BK=16, 4-stage ----------------
// 8 warps in 2x4 grid; warp tile 64x32. A fragments via ldmatrix.x4. KSPL>1: split-K over blockIdx.z.
template <int KCHUNK, int KFULL, int LDA, int LDB, int LDC, int KSPL, bool LUT, bool GELU>
__global__ __launch_bounds__(256, 2) void gemm_tf32(
    const float* __restrict__ Ain,   // x (LUT) / unused
    const float* __restrict__ Bin,   // w1 / w2 (expert-major)
    const float* __restrict__ bias)  // b1 (gemm2: unused)
{
    int e = blockIdx.z / KSPL;
    int ksp = blockIdx.z % KSPL;
    int cnt = g_count[e];
    int t0 = blockIdx.y * 128;
    if (t0 >= cnt) return;
    int n0 = blockIdx.x * 128;
    int kbase = ksp * KCHUNK;

    extern __shared__ char smem[];
    uint32_t sb = smem_to_u32(smem);
    int* rowsLUT = (int*)smem;
    int tid = threadIdx.x;
    int lane = tid & 31, wid = tid >> 5;
    int wm = wid >> 2, wn = wid & 3;

    if (LUT && tid < 128) rowsLUT[tid] = g_rows[e * 2048 + min(t0 + tid, cnt - 1)];
    __syncthreads();

    // cp.async setup: A = 2 x 16B per thread (rows r, r+64), B = 2 x 16B per thread
    const float* aptr[2];
    uint32_t adst[2];
#pragma unroll
    for (int i = 0; i < 2; i++) {
        int r = (tid >> 2) + 64 * i;
        const float* base;
        if (LUT) base = Ain + (size_t)rowsLUT[r] * LDA;
        else     base = (const float*)g_H + (size_t)(e * 2048 + t0 + r) * LDA;
        aptr[i] = base + kbase + (tid & 3) * 4;
        adst[i] = sb + SM_A + r * 80 + (tid & 3) * 16;
    }
    int kb = tid >> 5;
    const float* Bsrc = Bin + (size_t)e * KFULL * LDB + (size_t)kbase * LDB + n0 + (tid & 31) * 4;
    const float* bptr[2];
    uint32_t bdst[2];
#pragma unroll
    for (int j = 0; j < 2; j++) {
        bptr[j] = Bsrc + (size_t)(kb + 8 * j) * LDB;
        bdst[j] = sb + SM_B + (kb + 8 * j) * 544 + (tid & 31) * 16;
    }

    float c[4][4][4];
#pragma unroll
    for (int mt = 0; mt < 4; mt++)
#pragma unroll
        for (int nt = 0; nt < 4; nt++)
#pragma unroll
            for (int q = 0; q < 4; q++) c[mt][nt][q] = 0.f;

    // prologue
#pragma unroll
    for (int s = 0; s < STAGES - 1; s++) {
        int k0 = s * 16;
#pragma unroll
        for (int i = 0; i < 2; i++) cpa16(adst[i] + s * A_STAGE_B, aptr[i] + k0);
#pragma unroll
        for (int j = 0; j < 2; j++) cpa16(bdst[j] + s * B_STAGE_B, bptr[j] + (size_t)k0 * LDB);
        CP_COMMIT();
    }

    // ldmatrix lane base for A: matrices m0=rows g/k0-3, m1=g+8/k0-3, m2=g/k4-7, m3=g+8/k4-7
    int a_lm_row = wm * 64 + (lane & 7) + ((lane >> 3) & 1) * 8;
    uint32_t a_lm_base = sb + SM_A + a_lm_row * 80 + (lane >> 4) * 16;
    uint32_t b_frag_base = sb + SM_B + ((lane & 3) * 136 + wn * 32 + (lane >> 2)) * 4;

    const int NK = KCHUNK / 16;
    for (int kt = 0; kt < NK; kt++) {
        CP_WAIT(STAGES - 2);
        __syncthreads();
        int s = kt & (STAGES - 1);
        int knext = kt + STAGES - 1;
        if (knext < NK) {
            int sn = knext & (STAGES - 1);
            int k0 = knext * 16;
#pragma unroll
            for (int i = 0; i < 2; i++) cpa16(adst[i] + sn * A_STAGE_B, aptr[i] + k0);
#pragma unroll
            for (int j = 0; j < 2; j++) cpa16(bdst[j] + sn * B_STAGE_B, bptr[j] + (size_t)k0 * LDB);
            CP_COMMIT();
        }
        uint32_t ab = a_lm_base + s * A_STAGE_B;
        uint32_t bb = b_frag_base + s * B_STAGE_B;
#pragma unroll
        for (int ks = 0; ks < 2; ks++) {
            uint32_t af[4][4], bf[4][2];
#pragma unroll
            for (int mt = 0; mt < 4; mt++)
                ldsm4(af[mt], ab + mt * 1280 + ks * 32);
#pragma unroll
            for (int nt = 0; nt < 4; nt++) {
                uint32_t bd = bb + ks * 4352 + nt * 32;
                bf[nt][0] = lds32(bd);
                bf[nt][1] = lds32(bd + 2176);
            }
#pragma unroll
            for (int mt = 0; mt < 4; mt++)
#pragma unroll
                for (int nt = 0; nt < 4; nt++)
                    mma8(c[mt][nt], af[mt], bf[nt]);
        }
    }

    // epilogue
#pragma unroll
    for (int mt = 0; mt < 4; mt++) {
#pragma unroll
        for (int h = 0; h < 2; h++) {
            int lr = wm * 64 + mt * 16 + (lane >> 2) + h * 8;
            if (t0 + lr < cnt) {
                size_t rowoff = (size_t)(e * 2048 + t0 + lr) * LDC + n0 + wn * 32 + (lane & 3) * 2;
                if (GELU) {
                    const float* bias_e = bias + (size_t)e * LDC + n0 + wn * 32 + (lane & 3) * 2;
                    float* dst = g_H + rowoff;
#pragma unroll
                    for (int nt = 0; nt < 4; nt++) {
                        float2 bv = *(const float2*)(bias_e + nt * 8);
                        float v0 = c[mt][nt][h * 2 + 0] + bv.x;
                        float v1 = c[mt][nt][h * 2 + 1] + bv.y;
                        v0 = 0.5f * v0 * (1.0f + erff(v0 * 0.7071067811865476f));
                        v1 = 0.5f * v1 * (1.0f + erff(v1 * 0.7071067811865476f));
                        *(float2*)(dst + nt * 8) = make_float2(v0, v1);
                    }
                } else {
                    float* dst = g_Lp + (size_t)ksp * PARTSZ + rowoff;
#pragma unroll
                    for (int nt = 0; nt < 4; nt++)
                        *(float2*)(dst + nt * 8) =
                            make_float2(c[mt][nt][h * 2 + 0], c[mt][nt][h * 2 + 1]);
                }
            }
        }
    }
}

// Per-token: sum split-K partials + bias, logsumexp both expert rows, combine, log.
__global__ void combine_kernel(float* __restrict__ out, const float* __restrict__ b2) {
    int b = blockIdx.x;
    int tid = threadIdx.x;
    __shared__ float sred[256];
    int s0 = g_slot[b * 2], s1 = g_slot[b * 2 + 1];
    int e0 = s0 >> 11, e1 = s1 >> 11;
    float gg0 = g_gate[b * 2], gg1 = g_gate[b * 2 + 1];

    float v00, v01, v10, v11;
    {
        size_t r0 = (size_t)s0 * NO, r1 = (size_t)s1 * NO;
        v00 = b2[e0 * NO + tid]; v01 = b2[e0 * NO + tid + 256];
        v10 = b2[e1 * NO + tid]; v11 = b2[e1 * NO + tid + 256];
#pragma unroll
        for (int p = 0; p < KSPLIT2; p++) {
            const float* P = g_Lp + (size_t)p * PARTSZ;
            v00 += P[r0 + tid]; v01 += P[r0 + tid + 256];
            v10 += P[r1 + tid]; v11 += P[r1 + tid + 256];
        }
    }

    sred[tid] = fmaxf(v00, v01); __syncthreads();
    for (int s = 128; s; s >>= 1) { if (tid < s) sred[tid] = fmaxf(sred[tid], sred[tid + s]); __syncthreads(); }
    float m0 = sred[0]; __syncthreads();
    sred[tid] = expf(v00 - m0) + expf(v01 - m0); __syncthreads();
    for (int s = 128; s; s >>= 1) { if (tid < s) sred[tid] += sred[tid + s]; __syncthreads(); }
    float lse0 = m0 + logf(sred[0]); __syncthreads();

    sred[tid] = fmaxf(v10, v11); __syncthreads();
    for (int s = 128; s; s >>= 1) { if (tid < s) sred[tid] = fmaxf(sred[tid], sred[tid + s]); __syncthreads(); }
    float m1 = sred[0]; __syncthreads();
    sred[tid] = expf(v10 - m1) + expf(v11 - m1); __syncthreads();
    for (int s = 128; s; s >>= 1) { if (tid < s) sred[tid] += sred[tid + s]; __syncthreads(); }
    float lse1 = m1 + logf(sred[0]);

    out[(size_t)b * NO + tid]       = logf(gg0 * expf(v00 - lse0) + gg1 * expf(v10 - lse1));
    out[(size_t)b * NO + tid + 256] = logf(gg0 * expf(v01 - lse0) + gg1 * expf(v11 - lse1));
}

extern "C" void kernel_launch(void* const* d_in, const int* in_sizes, int n_in,
                              void* d_out, int out_size) {
    const float* x  = (const float*)d_in[0];
    const float* wg = (const float*)d_in[1];
    const float* w1 = (const float*)d_in[2];
    const float* b1 = (const float*)d_in[3];
    const float* w2 = (const float*)d_in[4];
    const float* b2 = (const float*)d_in[5];
    float* out = (float*)d_out;

    auto k1 = gemm_tf32<ND, ND, ND, NH, NH, 1, true, true>;
    auto k2 = gemm_tf32<NH / KSPLIT2, NH, NH, NO, NO, KSPLIT2, false, false>;
    cudaFuncSetAttribute((const void*)k1, cudaFuncAttributeMaxDynamicSharedMemorySize, SMEM_TOTAL);
    cudaFuncSetAttribute((const void*)k2, cudaFuncAttributeMaxDynamicSharedMemorySize, SMEM_TOTAL);

    zero_counts_kernel<<<1, 32>>>();
    gate_kernel<<<NB / 8, 256>>>(x, wg);
    k1<<<dim3(NH / 128, 16, NE), 256, SMEM_TOTAL>>>(x, w1, b1);
    k2<<<dim3(NO / 128, 16, NE * KSPLIT2), 256, SMEM_TOTAL>>>(x, w2, b2);
    combine_kernel<<<NB, 256>>>(out, b2);
}

// round 14
// speedup vs baseline: 1.4069x; 1.1074x over previous
#include <cuda_runtime.h>
#include <math.h>
#include <stdint.h>

#define NB 2048
#define ND 1024
#define NH 2048
#define NO 512
#define NE 8
#define KSPLIT2 4

#define STAGES 4
#define A_STAGE_B (128 * 80)   // 128 rows * 20 words * 4B
#define B_STAGE_B (16 * 544)   // 16 k-rows * 136 words * 4B
#define SM_A 1024
#define SM_B (SM_A + STAGES * A_STAGE_B)
#define SMEM_TOTAL (SM_B + STAGES * B_STAGE_B)   // 76800 B -> 2 CTAs/SM

// ---------------- scratch ----------------
__device__ float g_H[(size_t)NE * 2048 * NH];                // expert hidden (slot-major)
__device__ float g_Lp[(size_t)KSPLIT2 * NE * 2048 * NO];     // split-K partial logits
__device__ int   g_count[NE];
__device__ int   g_rows[NE * 2048];
__device__ int   g_slot[NB * 2];
__device__ float g_gate[NB * 2];

#define PARTSZ ((size_t)NE * 2048 * NO)

// ---------------- helpers ----------------
__device__ __forceinline__ uint32_t smem_to_u32(const void* p) {
    uint32_t a;
    asm("{ .reg .u64 t; cvta.to.shared.u64 t, %1; cvt.u32.u64 %0, t; }" : "=r"(a) : "l"(p));
    return a;
}
__device__ __forceinline__ void cpa16(uint32_t dst, const void* src) {
    asm volatile("cp.async.cg.shared.global [%0], [%1], 16;" :: "r"(dst), "l"(src));
}
#define CP_COMMIT() asm volatile("cp.async.commit_group;" ::: "memory")
#define CP_WAIT(n)  asm volatile("cp.async.wait_group %0;" :: "n"(n) : "memory")
__device__ __forceinline__ uint32_t lds32(uint32_t a) {
    uint32_t v;
    asm volatile("ld.shared.b32 %0, [%1];" : "=r"(v) : "r"(a));
    return v;
}
__device__ __forceinline__ void ldsm4(uint32_t* r, uint32_t a) {
    asm volatile("ldmatrix.sync.aligned.m8n8.x4.shared.b16 {%0,%1,%2,%3}, [%4];"
        : "=r"(r[0]), "=r"(r[1]), "=r"(r[2]), "=r"(r[3]) : "r"(a));
}
__device__ __forceinline__ void mma8(float* c, const uint32_t* a, const uint32_t* b) {
    asm volatile(
        "mma.sync.aligned.m16n8k8.row.col.f32.tf32.tf32.f32 "
        "{%0,%1,%2,%3}, {%4,%5,%6,%7}, {%8,%9}, {%0,%1,%2,%3};"
        : "+f"(c[0]), "+f"(c[1]), "+f"(c[2]), "+f"(c[3])
        : "r"(a[0]), "r"(a[1]), "r"(a[2]), "r"(a[3]), "r"(b[0]), "r"(b[1]));
}

__global__ void zero_counts_kernel() {
    if (threadIdx.x < NE) g_count[threadIdx.x] = 0;
}

// One warp per token: logits, top-2 (first-index ties), softmax-of-2, scatter.
__global__ void gate_kernel(const float* __restrict__ x, const float* __restrict__ wg) {
    int warp = threadIdx.x >> 5, lane = threadIdx.x & 31;
    int b = blockIdx.x * 8 + warp;
    float acc[NE];
#pragma unroll
    for (int e = 0; e < NE; e++) acc[e] = 0.f;
    const float* xr = x + (size_t)b * ND;
    for (int d = lane; d < ND; d += 32) {
        float xv = xr[d];
#pragma unroll
        for (int e = 0; e < NE; e++) acc[e] += xv * wg[d * NE + e];
    }
#pragma unroll
    for (int e = 0; e < NE; e++)
#pragma unroll
        for (int off = 16; off; off >>= 1)
            acc[e] += __shfl_xor_sync(0xffffffffu, acc[e], off);
    if (lane == 0) {
        int i0 = 0; float l0 = acc[0];
#pragma unroll
        for (int e = 1; e < NE; e++) if (acc[e] > l0) { l0 = acc[e]; i0 = e; }
        int i1 = (i0 == 0) ? 1 : 0;
        float l1 = acc[i1];
#pragma unroll
        for (int e = 0; e < NE; e++)
            if (e != i0 && acc[e] > l1) { l1 = acc[e]; i1 = e; }
        float ex = expf(l1 - l0);
        float inv = 1.f / (1.f + ex);
        int p0 = atomicAdd(&g_count[i0], 1);
        g_rows[i0 * 2048 + p0] = b;
        g_slot[b * 2 + 0] = i0 * 2048 + p0;
        g_gate[b * 2 + 0] = inv;
        int p1 = atomicAdd(&g_count[i1], 1);
        g_rows[i1 * 2048 + p1] = b;
        g_slot[b * 2 + 1] = i1 * 2048 + p1;
        g_gate[b * 2 + 1] = ex * inv;
    }
}

// ---------------- TF32 grouped GEMM: CTA 128x128, 256 threads, 2 CTAs/SM, BK=16, 4-stage ----------------
// 8 warps in 2x4 grid; warp tile 64x32. A fragments via ldmatrix.x4. KSPL>1: split-K over blockIdx.z.
// Publication-correct order: CP_WAIT then __syncthreads BEFORE any reads of the stage.
template <int KCHUNK, int KFULL, int LDA, int LDB, int LDC, int KSPL, bool LUT, bool GELU>
__global__ __launch_bounds__(256, 2) void gemm_tf32(
    const float* __restrict__ Ain,   // x (LUT) / unused
    const float* __restrict__ Bin,   // w1 / w2 (expert-major)
    const float* __restrict__ bias)  // b1 (gemm2: unused)
{
    int e = blockIdx.z / KSPL;
    int ksp = blockIdx.z % KSPL;
    int cnt = g_count[e];
    int t0 = blockIdx.y * 128;
    if (t0 >= cnt) return;
    int n0 = blockIdx.x * 128;
    int kbase = ksp * KCHUNK;

    extern __shared__ char smem[];
    uint32_t sb = smem_to_u32(smem);
    int* rowsLUT = (int*)smem;
    int tid = threadIdx.x;
    int lane = tid & 31, wid = tid >> 5;
    int wm = wid >> 2, wn = wid & 3;

    if (LUT && tid < 128) rowsLUT[tid] = g_rows[e * 2048 + min(t0 + tid, cnt - 1)];
    __syncthreads();

    // cp.async setup: A = 2 x 16B per thread (rows r, r+64), B = 2 x 16B per thread
    const float* aptr[2];
    uint32_t adst[2];
#pragma unroll
    for (int i = 0; i < 2; i++) {
        int r = (tid >> 2) + 64 * i;
        const float* base;
        if (LUT) base = Ain + (size_t)rowsLUT[r] * LDA;
        else     base = (const float*)g_H + (size_t)(e * 2048 + t0 + r) * LDA;
        aptr[i] = base + kbase + (tid & 3) * 4;
        adst[i] = sb + SM_A + r * 80 + (tid & 3) * 16;
    }
    int kb = tid >> 5;
    const float* Bsrc = Bin + (size_t)e * KFULL * LDB + (size_t)kbase * LDB + n0 + (tid & 31) * 4;
    const float* bptr[2];
    uint32_t bdst[2];
#pragma unroll
    for (int j = 0; j < 2; j++) {
        bptr[j] = Bsrc + (size_t)(kb + 8 * j) * LDB;
        bdst[j] = sb + SM_B + (kb + 8 * j) * 544 + (tid & 31) * 16;
    }

    float c[4][4][4];
#pragma unroll
    for (int mt = 0; mt < 4; mt++)
#pragma unroll
        for (int nt = 0; nt < 4; nt++)
#pragma unroll
            for (int q = 0; q < 4; q++) c[mt][nt][q] = 0.f;

    // prologue
#pragma unroll
    for (int s = 0; s < STAGES - 1; s++) {
        int k0 = s * 16;
#pragma unroll
        for (int i = 0; i < 2; i++) cpa16(adst[i] + s * A_STAGE_B, aptr[i] + k0);
#pragma unroll
        for (int j = 0; j < 2; j++) cpa16(bdst[j] + s * B_STAGE_B, bptr[j] + (size_t)k0 * LDB);
        CP_COMMIT();
    }

    // ldmatrix lane base for A: matrices m0=rows g/k0-3, m1=g+8/k0-3, m2=g/k4-7, m3=g+8/k4-7
    int a_lm_row = wm * 64 + (lane & 7) + ((lane >> 3) & 1) * 8;
    uint32_t a_lm_base = sb + SM_A + a_lm_row * 80 + (lane >> 4) * 16;
    uint32_t b_frag_base = sb + SM_B + ((lane & 3) * 136 + wn * 32 + (lane >> 2)) * 4;

    const int NK = KCHUNK / 16;
    for (int kt = 0; kt < NK; kt++) {
        // Each thread waits its OWN group kt, then the barrier publishes all
        // threads' stage-kt bytes before ANY thread reads them.
        CP_WAIT(STAGES - 2);
        __syncthreads();
        int s = kt & (STAGES - 1);
        uint32_t ab = a_lm_base + s * A_STAGE_B;
        uint32_t bb = b_frag_base + s * B_STAGE_B;

        // frags + mma for ks=0
        uint32_t af0[4][4], bf0[4][2];
#pragma unroll
        for (int mt = 0; mt < 4; mt++)
            ldsm4(af0[mt], ab + mt * 1280);
#pragma unroll
        for (int nt = 0; nt < 4; nt++) {
            bf0[nt][0] = lds32(bb + nt * 32);
            bf0[nt][1] = lds32(bb + 2176 + nt * 32);
        }
#pragma unroll
        for (int mt = 0; mt < 4; mt++)
#pragma unroll
            for (int nt = 0; nt < 4; nt++)
                mma8(c[mt][nt], af0[mt], bf0[nt]);

        // refill stage (kt+3)&3 == (kt-1)&3 — its readers consumed frags via mma
        // in iteration kt-1, before reaching this iteration's barrier.
        int knext = kt + STAGES - 1;
        if (knext < NK) {
            int sn = knext & (STAGES - 1);
            int k0 = knext * 16;
#pragma unroll
            for (int i = 0; i < 2; i++) cpa16(adst[i] + sn * A_STAGE_B, aptr[i] + k0);
#pragma unroll
            for (int j = 0; j < 2; j++) cpa16(bdst[j] + sn * B_STAGE_B, bptr[j] + (size_t)k0 * LDB);
        }
        CP_COMMIT();   // commit EVERY iteration (empty group in tail) so CP_WAIT(2)
                       // always guarantees group kt complete — tail-safe.

        // frags + mma for ks=1 (mma drains while the new cp.async group fills)
        uint32_t af1[4][4], bf1[4][2];
#pragma unroll
        for (int mt = 0; mt < 4; mt++)
            ldsm4(af1[mt], ab + mt * 1280 + 32);
#pragma unroll
        for (int nt = 0; nt < 4; nt++) {
            bf1[nt][0] = lds32(bb + 4352 + nt * 32);
            bf1[nt][1] = lds32(bb + 4352 + 2176 + nt * 32);
        }
#pragma unroll
        for (int mt = 0; mt < 4; mt++)
#pragma unroll
            for (int nt = 0; nt < 4; nt++)
                mma8(c[mt][nt], af1[mt], bf1[nt]);
    }

    // epilogue
#pragma unroll
    for (int mt = 0; mt < 4; mt++) {
#pragma unroll
        for (int h = 0; h < 2; h++) {
            int lr = wm * 64 + mt * 16 + (lane >> 2) + h * 8;
            if (t0 + lr < cnt) {
                size_t rowoff = (size_t)(e * 2048 + t0 + lr) * LDC + n0 + wn * 32 + (lane & 3) * 2;
                if (GELU) {
                    const float* bias_e = bias + (size_t)e * LDC + n0 + wn * 32 + (lane & 3) * 2;
                    float* dst = g_H + rowoff;
#pragma unroll
                    for (int nt = 0; nt < 4; nt++) {
                        float2 bv = *(const float2*)(bias_e + nt * 8);
                        float v0 = c[mt][nt][h * 2 + 0] + bv.x;
                        float v1 = c[mt][nt][h * 2 + 1] + bv.y;
                        v0 = 0.5f * v0 * (1.0f + erff(v0 * 0.7071067811865476f));
                        v1 = 0.5f * v1 * (1.0f + erff(v1 * 0.7071067811865476f));
                        *(float2*)(dst + nt * 8) = make_float2(v0, v1);
                    }
                } else {
                    float* dst = g_Lp + (size_t)ksp * PARTSZ + rowoff;
#pragma unroll
                    for (int nt = 0; nt < 4; nt++)
                        *(float2*)(dst + nt * 8) =
                            make_float2(c[mt][nt][h * 2 + 0], c[mt][nt][h * 2 + 1]);
                }
            }
        }
    }
}

// Per-token: sum split-K partials + bias, logsumexp both expert rows, combine, log.
__global__ void combine_kernel(float* __restrict__ out, const float* __restrict__ b2) {
    int b = blockIdx.x;
    int tid = threadIdx.x;
    __shared__ float sred[256];
    int s0 = g_slot[b * 2], s1 = g_slot[b * 2 + 1];
    int e0 = s0 >> 11, e1 = s1 >> 11;
    float gg0 = g_gate[b * 2], gg1 = g_gate[b * 2 + 1];

    float v00, v01, v10, v11;
    {
        size_t r0 = (size_t)s0 * NO, r1 = (size_t)s1 * NO;
        v00 = b2[e0 * NO + tid]; v01 = b2[e0 * NO + tid + 256];
        v10 = b2[e1 * NO + tid]; v11 = b2[e1 * NO + tid + 256];
#pragma unroll
        for (int p = 0; p < KSPLIT2; p++) {
            const float* P = g_Lp + (size_t)p * PARTSZ;
            v00 += P[r0 + tid]; v01 += P[r0 + tid + 256];
            v10 += P[r1 + tid]; v11 += P[r1 + tid + 256];
        }
    }

    sred[tid] = fmaxf(v00, v01); __syncthreads();
    for (int s = 128; s; s >>= 1) { if (tid < s) sred[tid] = fmaxf(sred[tid], sred[tid + s]); __syncthreads(); }
    float m0 = sred[0]; __syncthreads();
    sred[tid] = expf(v00 - m0) + expf(v01 - m0); __syncthreads();
    for (int s = 128; s; s >>= 1) { if (tid < s) sred[tid] += sred[tid + s]; __syncthreads(); }
    float lse0 = m0 + logf(sred[0]); __syncthreads();

    sred[tid] = fmaxf(v10, v11); __syncthreads();
    for (int s = 128; s; s >>= 1) { if (tid < s) sred[tid] = fmaxf(sred[tid], sred[tid + s]); __syncthreads(); }
    float m1 = sred[0]; __syncthreads();
    sred[tid] = expf(v10 - m1) + expf(v11 - m1); __syncthreads();
    for (int s = 128; s; s >>= 1) { if (tid < s) sred[tid] += sred[tid + s]; __syncthreads(); }
    float lse1 = m1 + logf(sred[0]);

    out[(size_t)b * NO + tid]       = logf(gg0 * expf(v00 - lse0) + gg1 * expf(v10 - lse1));
    out[(size_t)b * NO + tid + 256] = logf(gg0 * expf(v01 - lse0) + gg1 * expf(v11 - lse1));
}

extern "C" void kernel_launch(void* const* d_in, const int* in_sizes, int n_in,
                              void* d_out, int out_size) {
    const float* x  = (const float*)d_in[0];
    const float* wg = (const float*)d_in[1];
    const float* w1 = (const float*)d_in[2];
    const float* b1 = (const float*)d_in[3];
    const float* w2 = (const float*)d_in[4];
    const float* b2 = (const float*)d_in[5];
    float* out = (float*)d_out;

    auto k1 = gemm_tf32<ND, ND, ND, NH, NH, 1, true, true>;
    auto k2 = gemm_tf32<NH / KSPLIT2, NH, NH, NO, NO, KSPLIT2, false, false>;
    cudaFuncSetAttribute((const void*)k1, cudaFuncAttributeMaxDynamicSharedMemorySize, SMEM_TOTAL);
    cudaFuncSetAttribute((const void*)k2, cudaFuncAttributeMaxDynamicSharedMemorySize, SMEM_TOTAL);

    zero_counts_kernel<<<1, 32>>>();
    gate_kernel<<<NB / 8, 256>>>(x, wg);
    k1<<<dim3(NH / 128, 16, NE), 256, SMEM_TOTAL>>>(x, w1, b1);
    k2<<<dim3(NO / 128, 16, NE * KSPLIT2), 256, SMEM_TOTAL>>>(x, w2, b2);
    combine_kernel<<<NB, 256>>>(out, b2);
}

// round 15
// speedup vs baseline: 1.5095x; 1.0729x over previous
#include <cuda_runtime.h>
#include <math.h>
#include <stdint.h>

#define NB 2048
#define ND 1024
#define NH 2048
#define NO 512
#define NE 8
#define KSPLIT2 4

#define STAGES 4
#define A_STAGE_B (128 * 80)   // 128 rows * 20 words * 4B
#define B_STAGE_B (16 * 544)   // 16 k-rows * 136 words * 4B
#define SM_A 1024
#define SM_B (SM_A + STAGES * A_STAGE_B)
#define SMEM_TOTAL (SM_B + STAGES * B_STAGE_B)   // 76800 B -> 2 CTAs/SM

// ---------------- scratch ----------------
__device__ float g_H[(size_t)NE * 2048 * NH];                // expert hidden (slot-major)
__device__ float g_Lp[(size_t)KSPLIT2 * NE * 2048 * NO];     // split-K partial logits
__device__ int   g_count[NE];
__device__ int   g_rows[NE * 2048];
__device__ int   g_slot[NB * 2];
__device__ float g_gate[NB * 2];

#define PARTSZ ((size_t)NE * 2048 * NO)

// ---------------- helpers ----------------
__device__ __forceinline__ uint32_t smem_to_u32(const void* p) {
    uint32_t a;
    asm("{ .reg .u64 t; cvta.to.shared.u64 t, %1; cvt.u32.u64 %0, t; }" : "=r"(a) : "l"(p));
    return a;
}
__device__ __forceinline__ void cpa16(uint32_t dst, const void* src) {
    asm volatile("cp.async.cg.shared.global [%0], [%1], 16;" :: "r"(dst), "l"(src));
}
#define CP_COMMIT() asm volatile("cp.async.commit_group;" ::: "memory")
#define CP_WAIT(n)  asm volatile("cp.async.wait_group %0;" :: "n"(n) : "memory")
__device__ __forceinline__ uint32_t lds32(uint32_t a) {
    uint32_t v;
    asm volatile("ld.shared.b32 %0, [%1];" : "=r"(v) : "r"(a));
    return v;
}
__device__ __forceinline__ void ldsm4(uint32_t* r, uint32_t a) {
    asm volatile("ldmatrix.sync.aligned.m8n8.x4.shared.b16 {%0,%1,%2,%3}, [%4];"
        : "=r"(r[0]), "=r"(r[1]), "=r"(r[2]), "=r"(r[3]) : "r"(a));
}
__device__ __forceinline__ void mma8(float* c, const uint32_t* a, const uint32_t* b) {
    asm volatile(
        "mma.sync.aligned.m16n8k8.row.col.f32.tf32.tf32.f32 "
        "{%0,%1,%2,%3}, {%4,%5,%6,%7}, {%8,%9}, {%0,%1,%2,%3};"
        : "+f"(c[0]), "+f"(c[1]), "+f"(c[2]), "+f"(c[3])
        : "r"(a[0]), "r"(a[1]), "r"(a[2]), "r"(a[3]), "r"(b[0]), "r"(b[1]));
}

__global__ void zero_counts_kernel() {
    if (threadIdx.x < NE) g_count[threadIdx.x] = 0;
}

// One warp per token: logits, top-2 (first-index ties), softmax-of-2, scatter.
__global__ void gate_kernel(const float* __restrict__ x, const float* __restrict__ wg) {
    int warp = threadIdx.x >> 5, lane = threadIdx.x & 31;
    int b = blockIdx.x * 8 + warp;
    float acc[NE];
#pragma unroll
    for (int e = 0; e < NE; e++) acc[e] = 0.f;
    const float* xr = x + (size_t)b * ND;
    for (int d = lane; d < ND; d += 32) {
        float xv = xr[d];
#pragma unroll
        for (int e = 0; e < NE; e++) acc[e] += xv * wg[d * NE + e];
    }
#pragma unroll
    for (int e = 0; e < NE; e++)
#pragma unroll
        for (int off = 16; off; off >>= 1)
            acc[e] += __shfl_xor_sync(0xffffffffu, acc[e], off);
    if (lane == 0) {
        int i0 = 0; float l0 = acc[0];
#pragma unroll
        for (int e = 1; e < NE; e++) if (acc[e] > l0) { l0 = acc[e]; i0 = e; }
        int i1 = (i0 == 0) ? 1 : 0;
        float l1 = acc[i1];
#pragma unroll
        for (int e = 0; e < NE; e++)
            if (e != i0 && acc[e] > l1) { l1 = acc[e]; i1 = e; }
        float ex = expf(l1 - l0);
        float inv = 1.f / (1.f + ex);
        int p0 = atomicAdd(&g_count[i0], 1);
        g_rows[i0 * 2048 + p0] = b;
        g_slot[b * 2 + 0] = i0 * 2048 + p0;
        g_gate[b * 2 + 0] = inv;
        int p1 = atomicAdd(&g_count[i1], 1);
        g_rows[i1 * 2048 + p1] = b;
        g_slot[b * 2 + 1] = i1 * 2048 + p1;
        g_gate[b * 2 + 1] = ex * inv;
    }
}

// ---------------- TF32 grouped GEMM: CTA 128x128, 256 threads, 2 CTAs/SM, BK=16, 4-stage ----------------
// 8 warps in 2x4 grid; warp tile 64x32. A via ldmatrix.x4. ks1-mma software-pipelined across barrier.
template <int KCHUNK, int KFULL, int LDA, int LDB, int LDC, int KSPL, bool LUT, bool GELU>
__global__ __launch_bounds__(256, 2) void gemm_tf32(
    const float* __restrict__ Ain,   // x (LUT) / unused
    const float* __restrict__ Bin,   // w1 / w2 (expert-major)
    const float* __restrict__ bias)  // b1 (gemm2: unused)
{
    int e = blockIdx.z / KSPL;
    int ksp = blockIdx.z % KSPL;
    int cnt = g_count[e];
    int t0 = blockIdx.y * 128;
    if (t0 >= cnt) return;
    int n0 = blockIdx.x * 128;
    int kbase = ksp * KCHUNK;

    extern __shared__ char smem[];
    uint32_t sb = smem_to_u32(smem);
    int* rowsLUT = (int*)smem;
    int tid = threadIdx.x;
    int lane = tid & 31, wid = tid >> 5;
    int wm = wid >> 2, wn = wid & 3;

    if (LUT && tid < 128) rowsLUT[tid] = g_rows[e * 2048 + min(t0 + tid, cnt - 1)];
    __syncthreads();

    // cp.async setup: A = 2 x 16B per thread (rows r, r+64), B = 2 x 16B per thread
    const float* aptr[2];
    uint32_t adst[2];
#pragma unroll
    for (int i = 0; i < 2; i++) {
        int r = (tid >> 2) + 64 * i;
        const float* base;
        if (LUT) base = Ain + (size_t)rowsLUT[r] * LDA;
        else     base = (const float*)g_H + (size_t)(e * 2048 + t0 + r) * LDA;
        aptr[i] = base + kbase + (tid & 3) * 4;
        adst[i] = sb + SM_A + r * 80 + (tid & 3) * 16;
    }
    int kb = tid >> 5;
    const float* Bsrc = Bin + (size_t)e * KFULL * LDB + (size_t)kbase * LDB + n0 + (tid & 31) * 4;
    const float* bptr[2];
    uint32_t bdst[2];
#pragma unroll
    for (int j = 0; j < 2; j++) {
        bptr[j] = Bsrc + (size_t)(kb + 8 * j) * LDB;
        bdst[j] = sb + SM_B + (kb + 8 * j) * 544 + (tid & 31) * 16;
    }

    float c[4][4][4];
#pragma unroll
    for (int mt = 0; mt < 4; mt++)
#pragma unroll
        for (int nt = 0; nt < 4; nt++)
#pragma unroll
            for (int q = 0; q < 4; q++) c[mt][nt][q] = 0.f;

    // prologue: stages 0..2 (groups 0..2, group g = k-tile g)
#pragma unroll
    for (int s = 0; s < STAGES - 1; s++) {
        int k0 = s * 16;
#pragma unroll
        for (int i = 0; i < 2; i++) cpa16(adst[i] + s * A_STAGE_B, aptr[i] + k0);
#pragma unroll
        for (int j = 0; j < 2; j++) cpa16(bdst[j] + s * B_STAGE_B, bptr[j] + (size_t)k0 * LDB);
        CP_COMMIT();
    }

    // ldmatrix lane base for A: matrices m0=rows g/k0-3, m1=g+8/k0-3, m2=g/k4-7, m3=g+8/k4-7
    int a_lm_row = wm * 64 + (lane & 7) + ((lane >> 3) & 1) * 8;
    uint32_t a_lm_base = sb + SM_A + a_lm_row * 80 + (lane >> 4) * 16;
    uint32_t b_frag_base = sb + SM_B + ((lane & 3) * 136 + wn * 32 + (lane >> 2)) * 4;

    const int NK = KCHUNK / 16;
    uint32_t af0[4][4], bf0[4][2], af1[4][4], bf1[4][2];

    // ---- peel k-tile 0 ----
    CP_WAIT(STAGES - 2);
    __syncthreads();
    {
        uint32_t ab = a_lm_base;
        uint32_t bb = b_frag_base;
#pragma unroll
        for (int mt = 0; mt < 4; mt++) ldsm4(af0[mt], ab + mt * 1280);
#pragma unroll
        for (int nt = 0; nt < 4; nt++) {
            bf0[nt][0] = lds32(bb + nt * 32);
            bf0[nt][1] = lds32(bb + 2176 + nt * 32);
        }
#pragma unroll
        for (int mt = 0; mt < 4; mt++)
#pragma unroll
            for (int nt = 0; nt < 4; nt++)
                mma8(c[mt][nt], af0[mt], bf0[nt]);
#pragma unroll
        for (int mt = 0; mt < 4; mt++) ldsm4(af1[mt], ab + mt * 1280 + 32);
#pragma unroll
        for (int nt = 0; nt < 4; nt++) {
            bf1[nt][0] = lds32(bb + 4352 + nt * 32);
            bf1[nt][1] = lds32(bb + 4352 + 2176 + nt * 32);
        }
        // refill stage 3 (k-tile 3) — never yet read
        if (STAGES - 1 < NK) {
            int k0 = (STAGES - 1) * 16;
#pragma unroll
            for (int i = 0; i < 2; i++) cpa16(adst[i] + (STAGES - 1) * A_STAGE_B, aptr[i] + k0);
#pragma unroll
            for (int j = 0; j < 2; j++) cpa16(bdst[j] + (STAGES - 1) * B_STAGE_B, bptr[j] + (size_t)k0 * LDB);
        }
        CP_COMMIT();   // group 3
    }

    // ---- main loop: hoisted ks1-mma covers CP_WAIT + barrier + ldsm ----
    for (int kt = 1; kt < NK; kt++) {
        // drain previous k-tile's ks1 from registers (covers the wait below)
#pragma unroll
        for (int mt = 0; mt < 4; mt++)
#pragma unroll
            for (int nt = 0; nt < 4; nt++)
                mma8(c[mt][nt], af1[mt], bf1[nt]);

        CP_WAIT(STAGES - 2);   // groups <= kt complete (commit-per-iter; group g = k-tile g)
        __syncthreads();       // publish stage kt to all threads
        int s = kt & (STAGES - 1);
        uint32_t ab = a_lm_base + s * A_STAGE_B;
        uint32_t bb = b_frag_base + s * B_STAGE_B;

#pragma unroll
        for (int mt = 0; mt < 4; mt++) ldsm4(af0[mt], ab + mt * 1280);
#pragma unroll
        for (int nt = 0; nt < 4; nt++) {
            bf0[nt][0] = lds32(bb + nt * 32);
            bf0[nt][1] = lds32(bb + 2176 + nt * 32);
        }
#pragma unroll
        for (int mt = 0; mt < 4; mt++)
#pragma unroll
            for (int nt = 0; nt < 4; nt++)
                mma8(c[mt][nt], af0[mt], bf0[nt]);

#pragma unroll
        for (int mt = 0; mt < 4; mt++) ldsm4(af1[mt], ab + mt * 1280 + 32);
#pragma unroll
        for (int nt = 0; nt < 4; nt++) {
            bf1[nt][0] = lds32(bb + 4352 + nt * 32);
            bf1[nt][1] = lds32(bb + 4352 + 2176 + nt * 32);
        }

        // refill stage (kt+3)&3 == (kt-1)&3 — ldsm-read in iteration kt-1, before this barrier
        int knext = kt + STAGES - 1;
        if (knext < NK) {
            int sn = knext & (STAGES - 1);
            int k0 = knext * 16;
#pragma unroll
            for (int i = 0; i < 2; i++) cpa16(adst[i] + sn * A_STAGE_B, aptr[i] + k0);
#pragma unroll
            for (int j = 0; j < 2; j++) cpa16(bdst[j] + sn * B_STAGE_B, bptr[j] + (size_t)k0 * LDB);
        }
        CP_COMMIT();   // commit EVERY iteration (empty in tail) — tail-safe accounting
    }

    // drain final ks1
#pragma unroll
    for (int mt = 0; mt < 4; mt++)
#pragma unroll
        for (int nt = 0; nt < 4; nt++)
            mma8(c[mt][nt], af1[mt], bf1[nt]);

    // epilogue
#pragma unroll
    for (int mt = 0; mt < 4; mt++) {
#pragma unroll
        for (int h = 0; h < 2; h++) {
            int lr = wm * 64 + mt * 16 + (lane >> 2) + h * 8;
            if (t0 + lr < cnt) {
                size_t rowoff = (size_t)(e * 2048 + t0 + lr) * LDC + n0 + wn * 32 + (lane & 3) * 2;
                if (GELU) {
                    const float* bias_e = bias + (size_t)e * LDC + n0 + wn * 32 + (lane & 3) * 2;
                    float* dst = g_H + rowoff;
#pragma unroll
                    for (int nt = 0; nt < 4; nt++) {
                        float2 bv = *(const float2*)(bias_e + nt * 8);
                        float v0 = c[mt][nt][h * 2 + 0] + bv.x;
                        float v1 = c[mt][nt][h * 2 + 1] + bv.y;
                        v0 = 0.5f * v0 * (1.0f + erff(v0 * 0.7071067811865476f));
                        v1 = 0.5f * v1 * (1.0f + erff(v1 * 0.7071067811865476f));
                        *(float2*)(dst + nt * 8) = make_float2(v0, v1);
                    }
                } else {
                    float* dst = g_Lp + (size_t)ksp * PARTSZ + rowoff;
#pragma unroll
                    for (int nt = 0; nt < 4; nt++)
                        *(float2*)(dst + nt * 8) =
                            make_float2(c[mt][nt][h * 2 + 0], c[mt][nt][h * 2 + 1]);
                }
            }
        }
    }
}

// Per-token: sum split-K partials + bias, logsumexp both expert rows, combine, log.
__global__ void combine_kernel(float* __restrict__ out, const float* __restrict__ b2) {
    int b = blockIdx.x;
    int tid = threadIdx.x;
    __shared__ float sred[256];
    int s0 = g_slot[b * 2], s1 = g_slot[b * 2 + 1];
    int e0 = s0 >> 11, e1 = s1 >> 11;
    float gg0 = g_gate[b * 2], gg1 = g_gate[b * 2 + 1];

    float v00, v01, v10, v11;
    {
        size_t r0 = (size_t)s0 * NO, r1 = (size_t)s1 * NO;
        v00 = b2[e0 * NO + tid]; v01 = b2[e0 * NO + tid + 256];
        v10 = b2[e1 * NO + tid]; v11 = b2[e1 * NO + tid + 256];
#pragma unroll
        for (int p = 0; p < KSPLIT2; p++) {
            const float* P = g_Lp + (size_t)p * PARTSZ;
            v00 += P[r0 + tid]; v01 += P[r0 + tid + 256];
            v10 += P[r1 + tid]; v11 += P[r1 + tid + 256];
        }
    }

    sred[tid] = fmaxf(v00, v01); __syncthreads();
    for (int s = 128; s; s >>= 1) { if (tid < s) sred[tid] = fmaxf(sred[tid], sred[tid + s]); __syncthreads(); }
    float m0 = sred[0]; __syncthreads();
    sred[tid] = expf(v00 - m0) + expf(v01 - m0); __syncthreads();
    for (int s = 128; s; s >>= 1) { if (tid < s) sred[tid] += sred[tid + s]; __syncthreads(); }
    float lse0 = m0 + logf(sred[0]); __syncthreads();

    sred[tid] = fmaxf(v10, v11); __syncthreads();
    for (int s = 128; s; s >>= 1) { if (tid < s) sred[tid] = fmaxf(sred[tid], sred[tid + s]); __syncthreads(); }
    float m1 = sred[0]; __syncthreads();
    sred[tid] = expf(v10 - m1) + expf(v11 - m1); __syncthreads();
    for (int s = 128; s; s >>= 1) { if (tid < s) sred[tid] += sred[tid + s]; __syncthreads(); }
    float lse1 = m1 + logf(sred[0]);

    out[(size_t)b * NO + tid]       = logf(gg0 * expf(v00 - lse0) + gg1 * expf(v10 - lse1));
    out[(size_t)b * NO + tid + 256] = logf(gg0 * expf(v01 - lse0) + gg1 * expf(v11 - lse1));
}

extern "C" void kernel_launch(void* const* d_in, const int* in_sizes, int n_in,
                              void* d_out, int out_size) {
    const float* x  = (const float*)d_in[0];
    const float* wg = (const float*)d_in[1];
    const float* w1 = (const float*)d_in[2];
    const float* b1 = (const float*)d_in[3];
    const float* w2 = (const float*)d_in[4];
    const float* b2 = (const float*)d_in[5];
    float* out = (float*)d_out;

    auto k1 = gemm_tf32<ND, ND, ND, NH, NH, 1, true, true>;
    auto k2 = gemm_tf32<NH / KSPLIT2, NH, NH, NO, NO, KSPLIT2, false, false>;
    cudaFuncSetAttribute((const void*)k1, cudaFuncAttributeMaxDynamicSharedMemorySize, SMEM_TOTAL);
    cudaFuncSetAttribute((const void*)k2, cudaFuncAttributeMaxDynamicSharedMemorySize, SMEM_TOTAL);

    zero_counts_kernel<<<1, 32>>>();
    gate_kernel<<<NB / 8, 256>>>(x, wg);
    k1<<<dim3(NH / 128, 16, NE), 256, SMEM_TOTAL>>>(x, w1, b1);
    k2<<<dim3(NO / 128, 16, NE * KSPLIT2), 256, SMEM_TOTAL>>>(x, w2, b2);
    combine_kernel<<<NB, 256>>>(out, b2);
}